// round 12
// baseline (speedup 1.0000x reference)
#include <cuda_runtime.h>
#include <cstdint>
#include <cstddef>

#define BATCH 256
#define SEQ   512
#define INDIM 32
#define H0 64
#define H1 128
#define H2 256

typedef unsigned long long ull;

__device__ float g_pre [(size_t)BATCH * SEQ * 4 * H2];
__device__ float g_x1  [(size_t)BATCH * SEQ * H0];
__device__ float g_x2  [(size_t)BATCH * SEQ * H1];
__device__ float g_x3  [(size_t)BATCH * SEQ * H2];

__device__ __forceinline__ float sigf(float x)  { return 1.f / (1.f + __expf(-x)); }
__device__ __forceinline__ float tanhfast(float x) { return 2.f / (1.f + __expf(-2.f * x)) - 1.f; }

__device__ __forceinline__ void ffma2(ull& d, ull a, ull b) {
    asm("fma.rn.f32x2 %0, %1, %2, %3;" : "=l"(d) : "l"(a), "l"(b), "l"(d));
}
__device__ __forceinline__ ull add2(ull a, ull b) {
    ull r; asm("add.rn.f32x2 %0, %1, %2;" : "=l"(r) : "l"(a), "l"(b)); return r;
}
__device__ __forceinline__ ull dup2(float w) {
    ull r; asm("mov.b64 %0, {%1, %1};" : "=l"(r) : "f"(w)); return r;
}
__device__ __forceinline__ ull pack2(float x, float y) {
    ull r; asm("mov.b64 %0, {%1, %2};" : "=l"(r) : "f"(x), "f"(y)); return r;
}
__device__ __forceinline__ void unpk(ull v, float& lo, float& hi) {
    asm("mov.b64 {%0, %1}, %2;" : "=f"(lo), "=f"(hi) : "l"(v));
}
__device__ __forceinline__ uint32_t cvta_s(const void* p) {
    return (uint32_t)__cvta_generic_to_shared(p);
}
__device__ __forceinline__ void stc32(uint32_t la, unsigned rank, float v) {
    uint32_t ra;
    asm("mapa.shared::cluster.u32 %0, %1, %2;" : "=r"(ra) : "r"(la), "r"(rank));
    asm volatile("st.shared::cluster.f32 [%0], %1;" :: "r"(ra), "f"(v) : "memory");
}
__device__ __forceinline__ void cluster_arrive_() {
    asm volatile("barrier.cluster.arrive.aligned;" ::: "memory");
}
__device__ __forceinline__ void cluster_wait_() {
    asm volatile("barrier.cluster.wait.aligned;" ::: "memory");
}
__device__ __forceinline__ void cluster_sync_() { cluster_arrive_(); cluster_wait_(); }

// ---------------- input GEMM: C = X @ Wperm^T + bias, m = t*B + b -------------
// Output col n = original gate-row (n&3)*H + (n>>2): pre[t][b] has (i,f,g,o)
// interleaved per hidden unit. TN: X indexed [b][t][k] (layer-0 noise).
template <int K, int N, bool TN>
__global__ void __launch_bounds__(256) gemm_pre_kernel(
    const float* __restrict__ X, const float* __restrict__ W,
    const float* __restrict__ bih, const float* __restrict__ bhh,
    float* __restrict__ C)
{
    constexpr int BM = 128, BN = 64, BK = 32;
    constexpr int HN = N / 4;
    __shared__ float Xs[BK * BM];
    __shared__ float Wt[BK * BN];
    const int m0 = blockIdx.x * BM, n0 = blockIdx.y * BN, tid = threadIdx.x;

    ull acc2[4][4];
#pragma unroll
    for (int p = 0; p < 4; p++)
#pragma unroll
        for (int n = 0; n < 4; n++) acc2[p][n] = 0ull;

    const int tm = (tid >> 4) << 3;
    const int tn = (tid & 15) << 2;

    for (int k0 = 0; k0 < K; k0 += BK) {
#pragma unroll
        for (int i = 0; i < 4; i++) {
            int f4 = tid + i * 256, row = f4 >> 3, kk = (f4 & 7) << 2;
            size_t src;
            if (TN) {
                const int t = m0 >> 8;
                const int b = (m0 & 255) + row;
                src = ((size_t)b * SEQ + t) * K + k0 + kk;
            } else {
                src = (size_t)(m0 + row) * K + k0 + kk;
            }
            float4 v = *reinterpret_cast<const float4*>(&X[src]);
            Xs[(kk + 0) * BM + row] = v.x; Xs[(kk + 1) * BM + row] = v.y;
            Xs[(kk + 2) * BM + row] = v.z; Xs[(kk + 3) * BM + row] = v.w;
        }
#pragma unroll
        for (int i = 0; i < 2; i++) {
            int f4 = tid + i * 256, row = f4 >> 3, kk = (f4 & 7) << 2;
            const int n = n0 + row;
            const int orow = (n & 3) * HN + (n >> 2);
            float4 v = *reinterpret_cast<const float4*>(&W[(size_t)orow * K + k0 + kk]);
            Wt[(kk + 0) * BN + row] = v.x; Wt[(kk + 1) * BN + row] = v.y;
            Wt[(kk + 2) * BN + row] = v.z; Wt[(kk + 3) * BN + row] = v.w;
        }
        __syncthreads();
#pragma unroll
        for (int kk = 0; kk < BK; kk++) {
            float2 a01 = *reinterpret_cast<const float2*>(&Xs[kk * BM + tm + 0]);
            float2 a23 = *reinterpret_cast<const float2*>(&Xs[kk * BM + tm + 2]);
            float2 a45 = *reinterpret_cast<const float2*>(&Xs[kk * BM + tm + 4]);
            float2 a67 = *reinterpret_cast<const float2*>(&Xs[kk * BM + tm + 6]);
            float4 b = *reinterpret_cast<const float4*>(&Wt[kk * BN + tn]);
            ull a[4] = {pack2(a01.x, a01.y), pack2(a23.x, a23.y),
                        pack2(a45.x, a45.y), pack2(a67.x, a67.y)};
            ull bd[4] = {dup2(b.x), dup2(b.y), dup2(b.z), dup2(b.w)};
#pragma unroll
            for (int p = 0; p < 4; p++)
#pragma unroll
                for (int n = 0; n < 4; n++) ffma2(acc2[p][n], a[p], bd[n]);
        }
        __syncthreads();
    }

    float bb4[4];
#pragma unroll
    for (int nn = 0; nn < 4; nn++) {
        const int n = n0 + tn + nn;
        const int orow = (n & 3) * HN + (n >> 2);
        bb4[nn] = bih[orow] + bhh[orow];
    }
#pragma unroll
    for (int p = 0; p < 4; p++) {
        float e0[4], e1[4];
#pragma unroll
        for (int n = 0; n < 4; n++) unpk(acc2[p][n], e0[n], e1[n]);
        float4 o0 = {e0[0] + bb4[0], e0[1] + bb4[1], e0[2] + bb4[2], e0[3] + bb4[3]};
        float4 o1 = {e1[0] + bb4[0], e1[1] + bb4[1], e1[2] + bb4[2], e1[3] + bb4[3]};
        *reinterpret_cast<float4*>(&C[(size_t)(m0 + tm + 2 * p + 0) * N + n0 + tn]) = o0;
        *reinterpret_cast<float4*>(&C[(size_t)(m0 + tm + 2 * p + 1) * N + n0 + tn]) = o1;
    }
}

// ---------------- LSTM recurrence: register weights + warp butterfly reduce ----
// thread = (j, kh), kh = lane low bits. Weights for k-slice [kh*KR,+KR) of all
// 4 gates in REGISTERS. Per batch: KQ broadcast LDS.128 of h + 8 FFMA2 each,
// then log2(KH) shfl.bfly rounds all-reduce the 4 gate sums across kh — every
// lane ends with the full sum; lane kh keeps batches b == kh (mod KH). Act is
// register-local (c in regs, pre prefetched as LDG.128 one step ahead); h goes
// to all G cluster peers via st.shared::cluster; one cluster barrier per step,
// with xout store + pre(t+1) prefetch hidden under it. No smem reduce, no
// second sync; smem is just hs[2][NB][H].
template <int H, int G, int NB, int KH>
__global__ void __launch_bounds__(256, 1) lstm_recur_kernel(
    const float* __restrict__ pre, const float* __restrict__ Whh,
    float* __restrict__ xout)
{
    constexpr int JS  = H / G;      // units per CTA
    constexpr int KR  = H / KH;     // k per slice
    constexpr int KQ  = KR / 4;     // float4 quads per slice
    constexpr int CPT = NB / KH;    // cells per thread
    static_assert(JS * KH == 256, "map");
    static_assert(NB % KH == 0, "batch split");

    extern __shared__ float sm[];
    float* hs = sm;                 // [2][NB][H]

    const int tid = threadIdx.x;
    const int j   = tid / KH;
    const int kh  = tid & (KH - 1);
    const int grp = (G > 1) ? (blockIdx.x / G) : blockIdx.x;
    const int sl  = (G > 1) ? (blockIdx.x % G) : 0;
    const int b0  = grp * NB;
    const int j0  = sl * JS;

    // ---- weight slice -> registers ----
    ull wr[4][KR / 2];
#pragma unroll
    for (int g = 0; g < 4; g++) {
        const float4* wrow = reinterpret_cast<const float4*>(
            Whh + ((size_t)g * H + j0 + j) * H + kh * KR);
#pragma unroll
        for (int q = 0; q < KQ; q++) {
            float4 v = __ldg(wrow + q);
            wr[g][2 * q + 0] = pack2(v.x, v.y);
            wr[g][2 * q + 1] = pack2(v.z, v.w);
        }
    }

    for (int i = tid; i < 2 * NB * H; i += 256) hs[i] = 0.f;
    __syncthreads();
    if (G > 1) cluster_sync_();

    // ---- per-cell state (cell cc -> batch b = cc*KH + kh) ----
    float  c[CPT];
    float4 pin[CPT];
#pragma unroll
    for (int cc = 0; cc < CPT; cc++) {
        c[cc] = 0.f;
        const int b = cc * KH + kh;
        pin[cc] = __ldcs(reinterpret_cast<const float4*>(
            pre + ((size_t)(b0 + b)) * 4 * H + (size_t)(j0 + j) * 4));
    }

    for (int t = 0; t < SEQ; t++) {
        const float* hcur = hs + (t & 1) * NB * H;

        ull sums[CPT][4];
#pragma unroll
        for (int b = 0; b < NB; b++) {
            const float4* hb = reinterpret_cast<const float4*>(hcur + b * H) + kh * KQ;
            ull a0 = 0ull, a1 = 0ull, a2 = 0ull, a3 = 0ull;
#pragma unroll
            for (int q = 0; q < KQ; q++) {
                float4 h4 = hb[q];
                const ull hp0 = pack2(h4.x, h4.y);
                const ull hp1 = pack2(h4.z, h4.w);
                ffma2(a0, hp0, wr[0][2 * q + 0]);
                ffma2(a1, hp0, wr[1][2 * q + 0]);
                ffma2(a2, hp0, wr[2][2 * q + 0]);
                ffma2(a3, hp0, wr[3][2 * q + 0]);
                ffma2(a0, hp1, wr[0][2 * q + 1]);
                ffma2(a1, hp1, wr[1][2 * q + 1]);
                ffma2(a2, hp1, wr[2][2 * q + 1]);
                ffma2(a3, hp1, wr[3][2 * q + 1]);
            }
            // butterfly all-reduce across the KH k-slices (kh = lane low bits)
#pragma unroll
            for (int off = 1; off < KH; off <<= 1) {
                a0 = add2(a0, __shfl_xor_sync(0xffffffffu, a0, off));
                a1 = add2(a1, __shfl_xor_sync(0xffffffffu, a1, off));
                a2 = add2(a2, __shfl_xor_sync(0xffffffffu, a2, off));
                a3 = add2(a3, __shfl_xor_sync(0xffffffffu, a3, off));
            }
            if ((b & (KH - 1)) == kh) {
                sums[b / KH][0] = a0; sums[b / KH][1] = a1;
                sums[b / KH][2] = a2; sums[b / KH][3] = a3;
            }
        }

        // ---- activations (register-local) ----
        float hv[CPT];
#pragma unroll
        for (int cc = 0; cc < CPT; cc++) {
            float l0, u0, l1, u1, l2, u2, l3, u3;
            unpk(sums[cc][0], l0, u0); unpk(sums[cc][1], l1, u1);
            unpk(sums[cc][2], l2, u2); unpk(sums[cc][3], l3, u3);
            const float gi = l0 + u0 + pin[cc].x;
            const float gf = l1 + u1 + pin[cc].y;
            const float gg = l2 + u2 + pin[cc].z;
            const float go = l3 + u3 + pin[cc].w;
            c[cc] = sigf(gf) * c[cc] + sigf(gi) * tanhfast(gg);
            hv[cc] = sigf(go) * tanhfast(c[cc]);
        }

        // ---- publish h(t+1) ----
        float* hnext = hs + ((t + 1) & 1) * NB * H;
#pragma unroll
        for (int cc = 0; cc < CPT; cc++) {
            const int b = cc * KH + kh;
            float* dst = hnext + b * H + (j0 + j);
            if (G == 1) {
                *dst = hv[cc];
            } else {
                const uint32_t la = cvta_s(dst);
#pragma unroll
                for (unsigned d = 0; d < G; d++) stc32(la, d, hv[cc]);
            }
        }

        if (G > 1) cluster_arrive_();

        // hidden under the barrier: xout store + pre(t+1) prefetch
        const int tnx = (t + 1 < SEQ) ? t + 1 : t;
#pragma unroll
        for (int cc = 0; cc < CPT; cc++) {
            const int b = cc * KH + kh;
            xout[((size_t)t * BATCH + b0 + b) * H + (j0 + j)] = hv[cc];
            pin[cc] = __ldcs(reinterpret_cast<const float4*>(
                pre + ((size_t)tnx * BATCH + b0 + b) * 4 * H + (size_t)(j0 + j) * 4));
        }

        if (G > 1) cluster_wait_();
        else       __syncthreads();
    }
}

// ---------------- final linear (OUT_DIM=1) + tanh; x3 is [t][B][H2] -----------
__global__ void __launch_bounds__(256) final_kernel(
    const float* __restrict__ x3, const float* __restrict__ Wl,
    const float* __restrict__ bl, float* __restrict__ out)
{
    int m = (blockIdx.x * 256 + threadIdx.x) >> 5;   // m = t*B + b
    int lane = threadIdx.x & 31;
    const float* xr = x3 + (size_t)m * H2;
    float acc = 0.f;
#pragma unroll
    for (int i = 0; i < 8; i++) acc += xr[i * 32 + lane] * __ldg(&Wl[i * 32 + lane]);
#pragma unroll
    for (int off = 16; off; off >>= 1) acc += __shfl_xor_sync(0xffffffffu, acc, off);
    if (lane == 0) {
        const int t = m >> 8, b = m & 255;
        out[(size_t)b * SEQ + t] = tanhf(acc + bl[0]);
    }
}

// ---------------- launch ----------------
template <typename KernT>
static void launch_cluster(KernT kern, int grid, int G, int smem,
                           const float* pre, const float* Whh, float* xout)
{
    cudaLaunchConfig_t cfg = {};
    cfg.gridDim = dim3(grid, 1, 1);
    cfg.blockDim = dim3(256, 1, 1);
    cfg.dynamicSmemBytes = smem;
    cfg.stream = 0;
    cudaLaunchAttribute attr[1];
    attr[0].id = cudaLaunchAttributeClusterDimension;
    attr[0].val.clusterDim.x = G;
    attr[0].val.clusterDim.y = 1;
    attr[0].val.clusterDim.z = 1;
    cfg.attrs = attr;
    cfg.numAttrs = 1;
    cudaLaunchKernelEx(&cfg, kern, pre, Whh, xout);
}

extern "C" void kernel_launch(void* const* d_in, const int* in_sizes, int n_in,
                              void* d_out, int out_size)
{
    const float* noise = (const float*)d_in[0];
    const float* Wih0 = (const float*)d_in[1];
    const float* Whh0 = (const float*)d_in[2];
    const float* bih0 = (const float*)d_in[3];
    const float* bhh0 = (const float*)d_in[4];
    const float* Wih1 = (const float*)d_in[5];
    const float* Whh1 = (const float*)d_in[6];
    const float* bih1 = (const float*)d_in[7];
    const float* bhh1 = (const float*)d_in[8];
    const float* Wih2 = (const float*)d_in[9];
    const float* Whh2 = (const float*)d_in[10];
    const float* bih2 = (const float*)d_in[11];
    const float* bhh2 = (const float*)d_in[12];
    const float* Wl   = (const float*)d_in[13];
    const float* bl   = (const float*)d_in[14];
    float* out = (float*)d_out;

    float *pre, *x1, *x2, *x3;
    cudaGetSymbolAddress((void**)&pre, g_pre);
    cudaGetSymbolAddress((void**)&x1,  g_x1);
    cudaGetSymbolAddress((void**)&x2,  g_x2);
    cudaGetSymbolAddress((void**)&x3,  g_x3);

    // smem: hs[2][NB][H] floats only
    const int smem0 = 2 * 4  * H0 * 4;   //  2 KB
    const int smem1 = 2 * 4  * H1 * 4;   //  4 KB
    const int smem2 = 2 * 16 * H2 * 4;   // 32 KB

    const int MBLK = (BATCH * SEQ) / 128;

    gemm_pre_kernel<INDIM, 4 * H0, true><<<dim3(MBLK, (4 * H0) / 64), 256>>>(
        noise, Wih0, bih0, bhh0, pre);
    lstm_recur_kernel<H0, 1, 4, 4><<<64, 256, smem0>>>(pre, Whh0, x1);

    gemm_pre_kernel<H0, 4 * H1, false><<<dim3(MBLK, (4 * H1) / 64), 256>>>(
        x1, Wih1, bih1, bhh1, pre);
    launch_cluster(lstm_recur_kernel<H1, 2, 4, 4>, 128, 2, smem1, pre, Whh1, x2);

    gemm_pre_kernel<H1, 4 * H2, false><<<dim3(MBLK, (4 * H2) / 64), 256>>>(
        x2, Wih2, bih2, bhh2, pre);
    launch_cluster(lstm_recur_kernel<H2, 8, 16, 8>, 128, 8, smem2, pre, Whh2, x3);

    final_kernel<<<(BATCH * SEQ) / 8, 256>>>(x3, Wl, bl, out);
}

// round 15
// speedup vs baseline: 2.8000x; 2.8000x over previous
#include <cuda_runtime.h>
#include <cstdint>
#include <cstddef>

#define BATCH 256
#define SEQ   512
#define INDIM 32
#define H0 64
#define H1 128
#define H2 256

typedef unsigned long long ull;

__device__ float g_pre [(size_t)BATCH * SEQ * 4 * H2];
__device__ float g_x1  [(size_t)BATCH * SEQ * H0];
__device__ float g_x2  [(size_t)BATCH * SEQ * H1];
__device__ float g_x3  [(size_t)BATCH * SEQ * H2];

__device__ __forceinline__ float sigf(float x)  { return 1.f / (1.f + __expf(-x)); }
__device__ __forceinline__ float tanhfast(float x) { return 2.f / (1.f + __expf(-2.f * x)) - 1.f; }

__device__ __forceinline__ void ffma2(ull& d, ull a, ull b) {
    asm("fma.rn.f32x2 %0, %1, %2, %3;" : "=l"(d) : "l"(a), "l"(b), "l"(d));
}
__device__ __forceinline__ ull add2(ull a, ull b) {
    ull r; asm("add.rn.f32x2 %0, %1, %2;" : "=l"(r) : "l"(a), "l"(b)); return r;
}
__device__ __forceinline__ ull dup2(float w) {
    ull r; asm("mov.b64 %0, {%1, %1};" : "=l"(r) : "f"(w)); return r;
}
__device__ __forceinline__ ull pack2(float x, float y) {
    ull r; asm("mov.b64 %0, {%1, %2};" : "=l"(r) : "f"(x), "f"(y)); return r;
}
__device__ __forceinline__ void unpk(ull v, float& lo, float& hi) {
    asm("mov.b64 {%0, %1}, %2;" : "=f"(lo), "=f"(hi) : "l"(v));
}
__device__ __forceinline__ uint32_t cvta_s(const void* p) {
    return (uint32_t)__cvta_generic_to_shared(p);
}
__device__ __forceinline__ void stc32(uint32_t la, unsigned rank, float v) {
    uint32_t ra;
    asm("mapa.shared::cluster.u32 %0, %1, %2;" : "=r"(ra) : "r"(la), "r"(rank));
    asm volatile("st.shared::cluster.f32 [%0], %1;" :: "r"(ra), "f"(v) : "memory");
}
__device__ __forceinline__ void cluster_arrive_() {
    asm volatile("barrier.cluster.arrive.aligned;" ::: "memory");
}
__device__ __forceinline__ void cluster_wait_() {
    asm volatile("barrier.cluster.wait.aligned;" ::: "memory");
}
__device__ __forceinline__ void cluster_sync_() { cluster_arrive_(); cluster_wait_(); }

// ---------------- input GEMM: C = X @ Wperm^T + bias, m = t*B + b -------------
// Output col n = original gate-row (n&3)*H + (n>>2): pre[t][b] has (i,f,g,o)
// interleaved per hidden unit. TN: X indexed [b][t][k] (layer-0 noise).
template <int K, int N, bool TN>
__global__ void __launch_bounds__(256) gemm_pre_kernel(
    const float* __restrict__ X, const float* __restrict__ W,
    const float* __restrict__ bih, const float* __restrict__ bhh,
    float* __restrict__ C)
{
    constexpr int BM = 128, BN = 64, BK = 32;
    constexpr int HN = N / 4;
    __shared__ float Xs[BK * BM];
    __shared__ float Wt[BK * BN];
    const int m0 = blockIdx.x * BM, n0 = blockIdx.y * BN, tid = threadIdx.x;

    ull acc2[4][4];
#pragma unroll
    for (int p = 0; p < 4; p++)
#pragma unroll
        for (int n = 0; n < 4; n++) acc2[p][n] = 0ull;

    const int tm = (tid >> 4) << 3;
    const int tn = (tid & 15) << 2;

    for (int k0 = 0; k0 < K; k0 += BK) {
#pragma unroll
        for (int i = 0; i < 4; i++) {
            int f4 = tid + i * 256, row = f4 >> 3, kk = (f4 & 7) << 2;
            size_t src;
            if (TN) {
                const int t = m0 >> 8;
                const int b = (m0 & 255) + row;
                src = ((size_t)b * SEQ + t) * K + k0 + kk;
            } else {
                src = (size_t)(m0 + row) * K + k0 + kk;
            }
            float4 v = *reinterpret_cast<const float4*>(&X[src]);
            Xs[(kk + 0) * BM + row] = v.x; Xs[(kk + 1) * BM + row] = v.y;
            Xs[(kk + 2) * BM + row] = v.z; Xs[(kk + 3) * BM + row] = v.w;
        }
#pragma unroll
        for (int i = 0; i < 2; i++) {
            int f4 = tid + i * 256, row = f4 >> 3, kk = (f4 & 7) << 2;
            const int n = n0 + row;
            const int orow = (n & 3) * HN + (n >> 2);
            float4 v = *reinterpret_cast<const float4*>(&W[(size_t)orow * K + k0 + kk]);
            Wt[(kk + 0) * BN + row] = v.x; Wt[(kk + 1) * BN + row] = v.y;
            Wt[(kk + 2) * BN + row] = v.z; Wt[(kk + 3) * BN + row] = v.w;
        }
        __syncthreads();
#pragma unroll
        for (int kk = 0; kk < BK; kk++) {
            float2 a01 = *reinterpret_cast<const float2*>(&Xs[kk * BM + tm + 0]);
            float2 a23 = *reinterpret_cast<const float2*>(&Xs[kk * BM + tm + 2]);
            float2 a45 = *reinterpret_cast<const float2*>(&Xs[kk * BM + tm + 4]);
            float2 a67 = *reinterpret_cast<const float2*>(&Xs[kk * BM + tm + 6]);
            float4 b = *reinterpret_cast<const float4*>(&Wt[kk * BN + tn]);
            ull a[4] = {pack2(a01.x, a01.y), pack2(a23.x, a23.y),
                        pack2(a45.x, a45.y), pack2(a67.x, a67.y)};
            ull bd[4] = {dup2(b.x), dup2(b.y), dup2(b.z), dup2(b.w)};
#pragma unroll
            for (int p = 0; p < 4; p++)
#pragma unroll
                for (int n = 0; n < 4; n++) ffma2(acc2[p][n], a[p], bd[n]);
        }
        __syncthreads();
    }

    float bb4[4];
#pragma unroll
    for (int nn = 0; nn < 4; nn++) {
        const int n = n0 + tn + nn;
        const int orow = (n & 3) * HN + (n >> 2);
        bb4[nn] = bih[orow] + bhh[orow];
    }
#pragma unroll
    for (int p = 0; p < 4; p++) {
        float e0[4], e1[4];
#pragma unroll
        for (int n = 0; n < 4; n++) unpk(acc2[p][n], e0[n], e1[n]);
        float4 o0 = {e0[0] + bb4[0], e0[1] + bb4[1], e0[2] + bb4[2], e0[3] + bb4[3]};
        float4 o1 = {e1[0] + bb4[0], e1[1] + bb4[1], e1[2] + bb4[2], e1[3] + bb4[3]};
        *reinterpret_cast<float4*>(&C[(size_t)(m0 + tm + 2 * p + 0) * N + n0 + tn]) = o0;
        *reinterpret_cast<float4*>(&C[(size_t)(m0 + tm + 2 * p + 1) * N + n0 + tn]) = o1;
    }
}

// ---------------- LSTM recurrence: register weights + conflict-free smem reduce
// thread = (j, kh): unit j, k-slice [kh*KR,+KR). Weights for all 4 gates of the
// slice in REGISTERS as f32x2 pairs. Dot: per batch, KQ broadcast LDS.128 of h
// + 8 FFMA2 each; partials -> red[KH][NB][4][JS] (lane-stride 8B: conflict-free
// STS and LDS) -> one sync -> act cells cc*256+tid (jj lane-stride 1), tree-sum
// KH partials + pre(regs), c in regs, h to all G cluster peers (stc32); one
// cluster barrier per step with xout + pre(t+1) prefetch hidden under it.
template <int H, int G, int NB, int KH, int CPT>
__global__ void __launch_bounds__(256, 1) lstm_recur_kernel(
    const float* __restrict__ pre, const float* __restrict__ Whh,
    float* __restrict__ xout)
{
    constexpr int JS = H / G;       // units per CTA
    constexpr int KR = H / KH;      // k per slice
    constexpr int KQ = KR / 4;      // float4 quads per slice
    constexpr int CELLS = NB * JS;  // (batch, unit) cells per CTA
    static_assert(JS * KH == 256, "map");
    static_assert(CELLS <= 256 * CPT, "cells");

    extern __shared__ float sm[];
    float* hs = sm;                        // [2][NB][H]
    ull*   red = (ull*)(hs + 2 * NB * H);  // [KH][NB][4][JS]

    const int tid = threadIdx.x;
    const int j   = tid % JS;
    const int kh  = tid / JS;
    const int grp = (G > 1) ? (blockIdx.x / G) : blockIdx.x;
    const int sl  = (G > 1) ? (blockIdx.x % G) : 0;
    const int b0  = grp * NB;
    const int j0  = sl * JS;

    // ---- weight slice -> registers (one-time) ----
    ull wr[4][KR / 2];
#pragma unroll
    for (int g = 0; g < 4; g++) {
        const float4* wrow = reinterpret_cast<const float4*>(
            Whh + ((size_t)g * H + j0 + j) * H + kh * KR);
#pragma unroll
        for (int q = 0; q < KQ; q++) {
            float4 v = __ldg(wrow + q);
            wr[g][2 * q + 0] = pack2(v.x, v.y);
            wr[g][2 * q + 1] = pack2(v.z, v.w);
        }
    }

    for (int i = tid; i < 2 * NB * H; i += 256) hs[i] = 0.f;
    __syncthreads();
    if (G > 1) cluster_sync_();

    // ---- activation cells: cell cc*256 + tid -> (ab, jj); jj lane-stride 1 ----
    const int jj = tid % JS;
    int ab[CPT];
    bool act[CPT];
    float c[CPT];
    float4 pin[CPT];
#pragma unroll
    for (int cc = 0; cc < CPT; cc++) {
        const int cell = cc * 256 + tid;
        act[cc] = (cell < CELLS);
        ab[cc]  = act[cc] ? (cell / JS) : 0;
        c[cc]   = 0.f;
        if (act[cc])
            pin[cc] = __ldcs(reinterpret_cast<const float4*>(
                pre + (size_t)(b0 + ab[cc]) * 4 * H + (size_t)(j0 + jj) * 4));
    }

    for (int t = 0; t < SEQ; t++) {
        const float* hcur = hs + (t & 1) * NB * H;

        // ---- dot: all NB batches over this thread's k-slice ----
#pragma unroll
        for (int b = 0; b < NB; b++) {
            const float4* hb = reinterpret_cast<const float4*>(hcur + b * H) + kh * KQ;
            ull a0 = 0ull, a1 = 0ull, a2 = 0ull, a3 = 0ull;
#pragma unroll
            for (int q = 0; q < KQ; q++) {
                float4 h4 = hb[q];
                const ull hp0 = pack2(h4.x, h4.y);
                const ull hp1 = pack2(h4.z, h4.w);
                ffma2(a0, hp0, wr[0][2 * q + 0]);
                ffma2(a1, hp0, wr[1][2 * q + 0]);
                ffma2(a2, hp0, wr[2][2 * q + 0]);
                ffma2(a3, hp0, wr[3][2 * q + 0]);
                ffma2(a0, hp1, wr[0][2 * q + 1]);
                ffma2(a1, hp1, wr[1][2 * q + 1]);
                ffma2(a2, hp1, wr[2][2 * q + 1]);
                ffma2(a3, hp1, wr[3][2 * q + 1]);
            }
            ull* rp = red + ((size_t)(kh * NB + b) * 4) * JS + j;
            rp[0 * JS] = a0; rp[1 * JS] = a1; rp[2 * JS] = a2; rp[3 * JS] = a3;
        }
        __syncthreads();

        // ---- reduce (tree over KH) + activation ----
        float hv[CPT];
#pragma unroll
        for (int cc = 0; cc < CPT; cc++) {
            if (!act[cc]) continue;
            float gate[4];
#pragma unroll
            for (int g = 0; g < 4; g++) {
                ull v[KH];
#pragma unroll
                for (int kp = 0; kp < KH; kp++)
                    v[kp] = red[((size_t)(kp * NB + ab[cc]) * 4 + g) * JS + jj];
#pragma unroll
                for (int stride = KH / 2; stride >= 1; stride >>= 1)
#pragma unroll
                    for (int i = 0; i < stride; i++)
                        v[i] = add2(v[i], v[i + stride]);
                float lo, hi;
                unpk(v[0], lo, hi);
                gate[g] = lo + hi;
            }
            const float gi = gate[0] + pin[cc].x;
            const float gf = gate[1] + pin[cc].y;
            const float gg = gate[2] + pin[cc].z;
            const float go = gate[3] + pin[cc].w;
            c[cc] = sigf(gf) * c[cc] + sigf(gi) * tanhfast(gg);
            hv[cc] = sigf(go) * tanhfast(c[cc]);
        }

        // ---- publish h(t+1) (own smem or all cluster peers) ----
        float* hnext = hs + ((t + 1) & 1) * NB * H;
#pragma unroll
        for (int cc = 0; cc < CPT; cc++) {
            if (!act[cc]) continue;
            float* dst = hnext + ab[cc] * H + (j0 + jj);
            if (G == 1) {
                *dst = hv[cc];
            } else {
                const uint32_t la = cvta_s(dst);
#pragma unroll
                for (unsigned d = 0; d < G; d++) stc32(la, d, hv[cc]);
            }
        }

        if (G > 1) cluster_arrive_();

        // hidden under the barrier: xout store + pre(t+1) prefetch
        const int tnx = (t + 1 < SEQ) ? t + 1 : t;
#pragma unroll
        for (int cc = 0; cc < CPT; cc++) {
            if (!act[cc]) continue;
            xout[((size_t)t * BATCH + b0 + ab[cc]) * H + (j0 + jj)] = hv[cc];
            pin[cc] = __ldcs(reinterpret_cast<const float4*>(
                pre + ((size_t)tnx * BATCH + b0 + ab[cc]) * 4 * H + (size_t)(j0 + jj) * 4));
        }

        if (G > 1) cluster_wait_();
        else       __syncthreads();
    }
}

// ---------------- final linear (OUT_DIM=1) + tanh; x3 is [t][B][H2] -----------
__global__ void __launch_bounds__(256) final_kernel(
    const float* __restrict__ x3, const float* __restrict__ Wl,
    const float* __restrict__ bl, float* __restrict__ out)
{
    int m = (blockIdx.x * 256 + threadIdx.x) >> 5;   // m = t*B + b
    int lane = threadIdx.x & 31;
    const float* xr = x3 + (size_t)m * H2;
    float acc = 0.f;
#pragma unroll
    for (int i = 0; i < 8; i++) acc += xr[i * 32 + lane] * __ldg(&Wl[i * 32 + lane]);
#pragma unroll
    for (int off = 16; off; off >>= 1) acc += __shfl_xor_sync(0xffffffffu, acc, off);
    if (lane == 0) {
        const int t = m >> 8, b = m & 255;
        out[(size_t)b * SEQ + t] = tanhf(acc + bl[0]);
    }
}

// ---------------- launch ----------------
template <typename KernT>
static void launch_cluster(KernT kern, int grid, int G, int smem,
                           const float* pre, const float* Whh, float* xout)
{
    cudaLaunchConfig_t cfg = {};
    cfg.gridDim = dim3(grid, 1, 1);
    cfg.blockDim = dim3(256, 1, 1);
    cfg.dynamicSmemBytes = smem;
    cfg.stream = 0;
    cudaLaunchAttribute attr[1];
    attr[0].id = cudaLaunchAttributeClusterDimension;
    attr[0].val.clusterDim.x = G;
    attr[0].val.clusterDim.y = 1;
    attr[0].val.clusterDim.z = 1;
    cfg.attrs = attr;
    cfg.numAttrs = 1;
    cudaLaunchKernelEx(&cfg, kern, pre, Whh, xout);
}

extern "C" void kernel_launch(void* const* d_in, const int* in_sizes, int n_in,
                              void* d_out, int out_size)
{
    const float* noise = (const float*)d_in[0];
    const float* Wih0 = (const float*)d_in[1];
    const float* Whh0 = (const float*)d_in[2];
    const float* bih0 = (const float*)d_in[3];
    const float* bhh0 = (const float*)d_in[4];
    const float* Wih1 = (const float*)d_in[5];
    const float* Whh1 = (const float*)d_in[6];
    const float* bih1 = (const float*)d_in[7];
    const float* bhh1 = (const float*)d_in[8];
    const float* Wih2 = (const float*)d_in[9];
    const float* Whh2 = (const float*)d_in[10];
    const float* bih2 = (const float*)d_in[11];
    const float* bhh2 = (const float*)d_in[12];
    const float* Wl   = (const float*)d_in[13];
    const float* bl   = (const float*)d_in[14];
    float* out = (float*)d_out;

    float *pre, *x1, *x2, *x3;
    cudaGetSymbolAddress((void**)&pre, g_pre);
    cudaGetSymbolAddress((void**)&x1,  g_x1);
    cudaGetSymbolAddress((void**)&x2,  g_x2);
    cudaGetSymbolAddress((void**)&x3,  g_x3);

    // smem: hs[2][NB][H] f32 + red[KH][NB][4][JS] u64
    const int smem0 = 2 * 2 * H0 * 4   + 4 * 2 * 4 * 64 * 8;    //  17,408
    const int smem1 = 2 * 4 * H1 * 4   + 4 * 4 * 4 * 64 * 8;    //  36,864
    const int smem2 = 2 * 16 * H2 * 4  + 8 * 16 * 4 * 32 * 8;   // 163,840

    cudaFuncSetAttribute(lstm_recur_kernel<H0, 1, 2, 4, 1>,
                         cudaFuncAttributeMaxDynamicSharedMemorySize, smem0);
    cudaFuncSetAttribute(lstm_recur_kernel<H1, 2, 4, 4, 1>,
                         cudaFuncAttributeMaxDynamicSharedMemorySize, smem1);
    cudaFuncSetAttribute(lstm_recur_kernel<H2, 8, 16, 8, 2>,
                         cudaFuncAttributeMaxDynamicSharedMemorySize, smem2);

    const int MBLK = (BATCH * SEQ) / 128;

    gemm_pre_kernel<INDIM, 4 * H0, true><<<dim3(MBLK, (4 * H0) / 64), 256>>>(
        noise, Wih0, bih0, bhh0, pre);
    lstm_recur_kernel<H0, 1, 2, 4, 1><<<128, 256, smem0>>>(pre, Whh0, x1);

    gemm_pre_kernel<H0, 4 * H1, false><<<dim3(MBLK, (4 * H1) / 64), 256>>>(
        x1, Wih1, bih1, bhh1, pre);
    launch_cluster(lstm_recur_kernel<H1, 2, 4, 4, 1>, 128, 2, smem1, pre, Whh1, x2);

    gemm_pre_kernel<H1, 4 * H2, false><<<dim3(MBLK, (4 * H2) / 64), 256>>>(
        x2, Wih2, bih2, bhh2, pre);
    launch_cluster(lstm_recur_kernel<H2, 8, 16, 8, 2>, 128, 8, smem2, pre, Whh2, x3);

    final_kernel<<<(BATCH * SEQ) / 8, 256>>>(x3, Wl, bl, out);
}